// round 2
// baseline (speedup 1.0000x reference)
#include <cuda_runtime.h>
#include <math.h>

#define B_ 4
#define T_ 1024
#define H_ 512
#define P_ 20
#define V_ 32000
#define BT (B_*T_)
#define NB1 128

// ---------------- scratch (device globals; no allocation allowed) ----------------
__device__ float g_x[BT*H_];        // embedded input          8 MB
__device__ float g_xw[BT*4*H_];     // x @ Wih^T + biases     32 MB
__device__ float g_enc[BT*H_];      // LSTM1 hidden states     8 MB
__device__ float g_pxw[BT*4*P_];    // enc @ Wp_ih^T + biases
__device__ float g_mu[BT];
__device__ float g_sig[BT];
__device__ float g_ctx[BT*H_];      // attention context       8 MB
__device__ float g_comb[BT*H_];     // tanh combined           8 MB
__device__ unsigned g_bar_cnt;
__device__ unsigned g_bar_phase;

__device__ __forceinline__ float sigf(float x) { return 1.f / (1.f + expf(-x)); }

// ---------------- K0: embedding gather ----------------
__global__ void k_embed(const int* __restrict__ ids, const float* __restrict__ emb)
{
    int i = blockIdx.x * blockDim.x + threadIdx.x;
    if (i < BT * H_) {
        int bt = i >> 9;
        int h  = i & 511;
        g_x[i] = emb[(size_t)ids[bt] * H_ + h];
    }
}

// ---------------- generic SGEMM: C[m,n] = act( sum_k A(m,k)*Bw[n,k] + bias1[n] + bias2[n] )
// A is split at ksplit: k < ksplit reads A1 (row stride ksplit), else A2 (row stride K-ksplit).
// M fixed = 4096 (multiple of 128); N arbitrary (guarded); K multiple of 16.
__global__ __launch_bounds__(256)
void k_sgemm(const float* __restrict__ A1, const float* __restrict__ A2,
             int ksplit, int K, int N,
             const float* __restrict__ Bw,
             const float* __restrict__ bias1, const float* __restrict__ bias2,
             float* __restrict__ C, int act)
{
    __shared__ float As[16][132];
    __shared__ float Bs[16][132];
    const int tid = threadIdx.x;
    const int bm = blockIdx.y, bn = blockIdx.x;
    const int lrow = tid >> 2;          // 0..63
    const int lk4  = (tid & 3) << 2;    // 0,4,8,12
    const int tx = tid & 15, ty = tid >> 4;

    float acc[8][8];
#pragma unroll
    for (int i = 0; i < 8; i++)
#pragma unroll
        for (int j = 0; j < 8; j++) acc[i][j] = 0.f;

    for (int kt = 0; kt < K; kt += 16) {
        const float* Ab; int lda, kof;
        if (kt < ksplit) { Ab = A1; lda = ksplit;     kof = kt; }
        else             { Ab = A2; lda = K - ksplit; kof = kt - ksplit; }
#pragma unroll
        for (int rr = 0; rr < 128; rr += 64) {
            int row = lrow + rr;
            float4 va = *(const float4*)(Ab + (size_t)(bm * 128 + row) * lda + kof + lk4);
            As[lk4 + 0][row] = va.x; As[lk4 + 1][row] = va.y;
            As[lk4 + 2][row] = va.z; As[lk4 + 3][row] = va.w;
            int nrow = bn * 128 + row;
            float4 vb = make_float4(0.f, 0.f, 0.f, 0.f);
            if (nrow < N) vb = *(const float4*)(Bw + (size_t)nrow * K + kt + lk4);
            Bs[lk4 + 0][row] = vb.x; Bs[lk4 + 1][row] = vb.y;
            Bs[lk4 + 2][row] = vb.z; Bs[lk4 + 3][row] = vb.w;
        }
        __syncthreads();
#pragma unroll
        for (int k = 0; k < 16; ++k) {
            float4 a0 = *(const float4*)&As[k][ty * 8];
            float4 a1 = *(const float4*)&As[k][ty * 8 + 4];
            float4 b0 = *(const float4*)&Bs[k][tx * 8];
            float4 b1 = *(const float4*)&Bs[k][tx * 8 + 4];
            float av[8] = {a0.x, a0.y, a0.z, a0.w, a1.x, a1.y, a1.z, a1.w};
            float bv[8] = {b0.x, b0.y, b0.z, b0.w, b1.x, b1.y, b1.z, b1.w};
#pragma unroll
            for (int i = 0; i < 8; i++)
#pragma unroll
                for (int j = 0; j < 8; j++)
                    acc[i][j] = fmaf(av[i], bv[j], acc[i][j]);
        }
        __syncthreads();
    }

#pragma unroll
    for (int i = 0; i < 8; i++) {
        int m = bm * 128 + ty * 8 + i;
#pragma unroll
        for (int j = 0; j < 8; j++) {
            int n = bn * 128 + tx * 8 + j;
            if (n < N) {
                float v = acc[i][j] + bias1[n] + (bias2 ? bias2[n] : 0.f);
                if (act) v = tanhf(v);
                C[(size_t)m * N + n] = v;
            }
        }
    }
}

// ---------------- K2: LSTM-1 persistent kernel ----------------
// 128 blocks; block owns 4 hidden units (all 4 gates, all 4 batches).
// Whh slice (16 rows x 512) cached in smem. h exchanged via g_enc + global barrier.
__global__ __launch_bounds__(256)
void k_lstm1(const float* __restrict__ Whh)
{
    __shared__ float wsm[16][512];   // [gate*4+uu][k]
    __shared__ float hsm[2048];      // h_{t-1}: [b*512+k]
    __shared__ float gsum[64];       // [(gate*4+uu)*4 + b]
    __shared__ float csm[16];        // c state [uu*4+b]
    const int tid  = threadIdx.x;
    const int u0   = blockIdx.x * 4;
    const int warp = tid >> 5, lane = tid & 31;

    for (int i = tid; i < 16 * 512; i += 256) {
        int r = i >> 9, k = i & 511;
        wsm[r][k] = Whh[(size_t)((r >> 2) * 512 + u0 + (r & 3)) * 512 + k];
    }
    if (tid < 16) csm[tid] = 0.f;
    unsigned base = 0;
    if (tid == 0) base = *(volatile unsigned*)&g_bar_phase;
    __syncthreads();

    for (int t = 0; t < T_; ++t) {
        // prefetch this step's input-gate preactivations (independent of h)
        float xg[4];
        if (tid < 16) {
            int uu = tid >> 2, b = tid & 3;
            const float* xr = g_xw + (size_t)(b * T_ + t) * 2048 + u0 + uu;
            xg[0] = xr[0]; xg[1] = xr[512]; xg[2] = xr[1024]; xg[3] = xr[1536];
        }
        // load h_{t-1}
        if (t > 0) {
            for (int i = tid; i < 512; i += 256) {
                int b = i >> 7, k4 = i & 127;
                ((float4*)hsm)[i] =
                    ((const float4*)(g_enc + (size_t)(b * T_ + t - 1) * 512))[k4];
            }
        } else {
            for (int i = tid; i < 2048; i += 256) hsm[i] = 0.f;
        }
        __syncthreads();

        // 64 dot products of length 512; warp w handles tasks [w*8, w*8+8)
#pragma unroll
        for (int s = 0; s < 8; ++s) {
            int task = warp * 8 + s;
            int r = task >> 2, b = task & 3;
            const float4* wv = (const float4*)wsm[r];
            const float4* hv = (const float4*)(hsm + b * 512);
            float sum = 0.f;
#pragma unroll
            for (int q = 0; q < 4; ++q) {
                float4 w4 = wv[q * 32 + lane];
                float4 h4 = hv[q * 32 + lane];
                sum = fmaf(w4.x, h4.x, fmaf(w4.y, h4.y,
                      fmaf(w4.z, h4.z, fmaf(w4.w, h4.w, sum))));
            }
            sum += __shfl_down_sync(0xffffffffu, sum, 16);
            sum += __shfl_down_sync(0xffffffffu, sum, 8);
            sum += __shfl_down_sync(0xffffffffu, sum, 4);
            sum += __shfl_down_sync(0xffffffffu, sum, 2);
            sum += __shfl_down_sync(0xffffffffu, sum, 1);
            if (lane == 0) gsum[task] = sum;
        }
        __syncthreads();

        if (tid < 16) {
            int uu = tid >> 2, b = tid & 3;
            float gi = gsum[((0 * 4 + uu) << 2) | b] + xg[0];
            float gf = gsum[((1 * 4 + uu) << 2) | b] + xg[1];
            float gg = gsum[((2 * 4 + uu) << 2) | b] + xg[2];
            float go = gsum[((3 * 4 + uu) << 2) | b] + xg[3];
            float c = sigf(gf) * csm[tid] + sigf(gi) * tanhf(gg);
            csm[tid] = c;
            float h = sigf(go) * tanhf(c);
            g_enc[(size_t)(b * T_ + t) * 512 + u0 + uu] = h;
            __threadfence();
        }
        __syncthreads();

        // global sense-reversing barrier across 128 co-resident blocks
        if (tid == 0) {
            unsigned a = atomicAdd(&g_bar_cnt, 1u);
            if (a == NB1 - 1) {
                atomicExch(&g_bar_cnt, 0u);
                __threadfence();
                atomicAdd(&g_bar_phase, 1u);
            } else {
                while ((*(volatile unsigned*)&g_bar_phase) - base < (unsigned)(t + 1)) { }
            }
        }
        __syncthreads();
    }
}

// ---------------- K4: LSTM-2 (P=20) + mu/sigma scan, single block ----------------
__global__ __launch_bounds__(128)
void k_lstm2(const float* __restrict__ Wp_hh,
             const float* __restrict__ Wmu, const float* __restrict__ bmu,
             const float* __restrict__ Wsig, const float* __restrict__ bsig,
             const int* __restrict__ pad)
{
    __shared__ float wp[80][20];
    __shared__ float hp[4][20];
    __shared__ float cp[4][20];
    __shared__ float gp[4][80];
    __shared__ float wmu_s[3][20];
    __shared__ float wsig_s[20];
    __shared__ float mu_prev[4];
    __shared__ float invL[4];
    const int tid = threadIdx.x;

    for (int i = tid; i < 1600; i += 128) wp[i / 20][i % 20] = Wp_hh[i];
    for (int i = tid; i < 60; i += 128) wmu_s[i / 20][i % 20] = Wmu[i];
    if (tid < 20) wsig_s[tid] = Wsig[tid];
    if (tid < 80) { hp[tid / 20][tid % 20] = 0.f; cp[tid / 20][tid % 20] = 0.f; }
    if (tid < 4)  { mu_prev[tid] = 0.f; invL[tid] = 1.f / (float)pad[tid]; }
    __syncthreads();

    for (int t = 0; t < T_; ++t) {
        for (int i = tid; i < 320; i += 128) {
            int b = i / 80, r = i % 80;
            float s = g_pxw[(size_t)(b * T_ + t) * 80 + r];
#pragma unroll
            for (int k = 0; k < 20; ++k) s = fmaf(wp[r][k], hp[b][k], s);
            gp[b][r] = s;
        }
        __syncthreads();
        if (tid < 80) {
            int b = tid / 20, u = tid % 20;
            float c = sigf(gp[b][20 + u]) * cp[b][u] + sigf(gp[b][u]) * tanhf(gp[b][40 + u]);
            cp[b][u] = c;
            hp[b][u] = sigf(gp[b][60 + u]) * tanhf(c);
        }
        __syncthreads();
        if (tid < 4) {
            int b = tid;
            float m0 = bmu[0], m1 = bmu[1], m2 = bmu[2], sg = bsig[0];
#pragma unroll
            for (int k = 0; k < 20; ++k) {
                float h = hp[b][k];
                m0 = fmaf(wmu_s[0][k], h, m0);
                m1 = fmaf(wmu_s[1][k], h, m1);
                m2 = fmaf(wmu_s[2][k], h, m2);
                sg = fmaf(wsig_s[k], h, sg);
            }
            m0 = fmaxf(m0, 0.f); m1 = fmaxf(m1, 0.f); m2 = fmaxf(m2, 0.f);
            sg = sigf(sg);
            float base_ = (m1 + m2 * (float)(t + 1)) * invL[b];
            float mu = fmaf(m0, mu_prev[b], base_);
            mu_prev[b] = mu;
            g_mu[b * T_ + t]  = mu;
            g_sig[b * T_ + t] = sg;
        }
        __syncthreads();
    }
}

// ---------------- K5: attention weights + context, one block per (b,j) ----------------
__global__ __launch_bounds__(256)
void k_attn()
{
    __shared__ float wsm[1024];
    __shared__ float red[256];
    const int tid = threadIdx.x;
    const int bj = blockIdx.x;
    const int b = bj >> 10, j = bj & 1023;
    const float mu = g_mu[bj];
    const float sg = g_sig[bj];
    const float invd  = 1.f / (2.f * sg * sg + 0.001f);
    const float invj1 = 1.f / (float)(j + 1);

    float lsum = 0.f;
    for (int t = tid; t < 1024; t += 256) {
        float w = 0.f;
        if (t <= j) {
            float r = (float)t * invj1 - mu;
            w = expf(-r * r * invd);
        }
        wsm[t] = w;
        lsum += w;
    }
    red[tid] = lsum;
    __syncthreads();
    for (int s = 128; s > 0; s >>= 1) {
        if (tid < s) red[tid] += red[tid + s];
        __syncthreads();
    }
    const float scale = 1.f / fmaxf(red[0], 1e-12f);

    const float2* encb = (const float2*)(g_enc + (size_t)b * T_ * 512);
    float2 acc = make_float2(0.f, 0.f);
#pragma unroll 4
    for (int t = 0; t <= j; ++t) {
        float w = wsm[t];
        float2 e = encb[t * 256 + tid];
        acc.x = fmaf(w, e.x, acc.x);
        acc.y = fmaf(w, e.y, acc.y);
    }
    acc.x *= scale; acc.y *= scale;
    ((float2*)g_ctx)[(size_t)bj * 256 + tid] = acc;
}

// ---------------- launch ----------------
extern "C" void kernel_launch(void* const* d_in, const int* in_sizes, int n_in,
                              void* d_out, int out_size)
{
    const int*   ids      = (const int*)d_in[0];
    const int*   pad      = (const int*)d_in[1];
    const float* emb      = (const float*)d_in[2];
    const float* dec_bias = (const float*)d_in[3];
    const float* Wih      = (const float*)d_in[4];
    const float* Whh      = (const float*)d_in[5];
    const float* bih      = (const float*)d_in[6];
    const float* bhh      = (const float*)d_in[7];
    const float* Wp_ih    = (const float*)d_in[8];
    const float* Wp_hh    = (const float*)d_in[9];
    const float* bp_ih    = (const float*)d_in[10];
    const float* bp_hh    = (const float*)d_in[11];
    const float* Wmu      = (const float*)d_in[12];
    const float* bmu      = (const float*)d_in[13];
    const float* Wsig     = (const float*)d_in[14];
    const float* bsig     = (const float*)d_in[15];
    const float* Wc       = (const float*)d_in[16];
    const float* bc       = (const float*)d_in[17];
    float* out = (float*)d_out;

    float *p_x, *p_xw, *p_enc, *p_pxw, *p_ctx, *p_comb;
    cudaGetSymbolAddress((void**)&p_x,    g_x);
    cudaGetSymbolAddress((void**)&p_xw,   g_xw);
    cudaGetSymbolAddress((void**)&p_enc,  g_enc);
    cudaGetSymbolAddress((void**)&p_pxw,  g_pxw);
    cudaGetSymbolAddress((void**)&p_ctx,  g_ctx);
    cudaGetSymbolAddress((void**)&p_comb, g_comb);

    // K0: embedding
    k_embed<<<(BT * H_ + 255) / 256, 256>>>(ids, emb);
    // K1: xW = x @ Wih^T + bih + bhh   -> [4096, 2048]
    k_sgemm<<<dim3(2048 / 128, BT / 128), 256>>>(p_x, nullptr, 512, 512, 2048,
                                                 Wih, bih, bhh, p_xw, 0);
    // K2: LSTM-1 recurrence -> enc
    k_lstm1<<<NB1, 256>>>(Whh);
    // K3: pxW = enc @ Wp_ih^T + bp_ih + bp_hh -> [4096, 80]
    k_sgemm<<<dim3(1, BT / 128), 256>>>(p_enc, nullptr, 512, 512, 80,
                                        Wp_ih, bp_ih, bp_hh, p_pxw, 0);
    // K4: LSTM-2 + mu/sigma scan
    k_lstm2<<<1, 128>>>(Wp_hh, Wmu, bmu, Wsig, bsig, pad);
    // K5: attention + context
    k_attn<<<BT, 256>>>();
    // K6: combined = tanh([ctx, enc] @ Wc^T + bc) -> [4096, 512]
    k_sgemm<<<dim3(512 / 128, BT / 128), 256>>>(p_ctx, p_enc, 512, 1024, 512,
                                                Wc, bc, nullptr, p_comb, 1);
    // K7: logits = combined @ emb^T + dec_bias -> [4096, 32000]
    k_sgemm<<<dim3((V_ + 127) / 128, BT / 128), 256>>>(p_comb, nullptr, 512, 512, V_,
                                                       emb, dec_bias, nullptr, out, 0);
}

// round 4
// speedup vs baseline: 1.2252x; 1.2252x over previous
#include <cuda_runtime.h>
#include <cuda_bf16.h>
#include <cstdint>
#include <math.h>

#define B_ 4
#define T_ 1024
#define H_ 512
#define P_ 20
#define V_ 32000
#define BT (B_*T_)
#define NB1 128

// ---------------- scratch (device globals; no allocation allowed) ----------------
__device__ float g_xw[BT*4*H_];     // x @ Wih^T + biases     32 MB
__device__ float g_enc[BT*H_];      // LSTM1 hidden states     8 MB
__device__ float g_pxw[BT*4*P_];    // enc @ Wp_ih^T + biases
__device__ float g_mu[BT];
__device__ float g_sig[BT];
__device__ float g_ctx[BT*H_];      // attention context       8 MB
__device__ float g_comb[BT*H_];     // tanh combined           8 MB
__device__ unsigned g_bar_cnt;
__device__ unsigned g_bar_phase;

// bf16 split buffers for mma GEMMs
__device__ __nv_bfloat16 g_emb_hi[V_*H_];
__device__ __nv_bfloat16 g_emb_lo[V_*H_];
__device__ __nv_bfloat16 g_wih_hi[4*H_*H_];
__device__ __nv_bfloat16 g_wih_lo[4*H_*H_];
__device__ __nv_bfloat16 g_x_hi[BT*H_];
__device__ __nv_bfloat16 g_x_lo[BT*H_];
__device__ __nv_bfloat16 g_comb_hi[BT*H_];
__device__ __nv_bfloat16 g_comb_lo[BT*H_];

__device__ __forceinline__ float sigf(float x) { return 1.f / (1.f + expf(-x)); }

__device__ __forceinline__ uint32_t smem_u32(const void* p) {
    uint32_t a;
    asm("{ .reg .u64 t; cvta.to.shared.u64 t, %1; cvt.u32.u64 %0, t; }"
        : "=r"(a) : "l"(p));
    return a;
}

// ---------------- split fp32 -> bf16 hi/lo ----------------
__global__ void k_split(const float* __restrict__ src,
                        __nv_bfloat16* __restrict__ hi,
                        __nv_bfloat16* __restrict__ lo, int n)
{
    int i = blockIdx.x * blockDim.x + threadIdx.x;
    if (i < n) {
        float v = src[i];
        __nv_bfloat16 h = __float2bfloat16(v);
        hi[i] = h;
        lo[i] = __float2bfloat16(v - __bfloat162float(h));
    }
}

// ---------------- embedding gather (bf16 hi/lo) ----------------
__global__ void k_embed_bf(const int* __restrict__ ids)
{
    int i = blockIdx.x * blockDim.x + threadIdx.x;
    if (i < BT * H_) {
        int bt = i >> 9;
        int h  = i & 511;
        size_t src = (size_t)ids[bt] * H_ + h;
        g_x_hi[i] = g_emb_hi[src];
        g_x_lo[i] = g_emb_lo[src];
    }
}

// ---------------- mma.sync bf16x3 GEMM ----------------
// C[m,n] = sum_k A(m,k)*B(n,k) + bias1[n] (+bias2[n])
// A: [4096, 512] bf16 hi/lo; B: [N, 512] bf16 hi/lo; K-major. N mult of 128.
// 256 thr = 8 warps (2m x 4n), warp tile 64x32, K-chunks of 64, 8 chunks.
#define MMA_SMEM (4 * 16384)

#define LDSM4(r0, r1, r2, r3, a)                                             \
    asm volatile("ldmatrix.sync.aligned.m8n8.x4.shared.b16 {%0,%1,%2,%3}, [%4];" \
        : "=r"(r0), "=r"(r1), "=r"(r2), "=r"(r3) : "r"(a))

#define MMA16816(c, A0, A1, A2, A3, B0, B1)                                  \
    asm volatile("mma.sync.aligned.m16n8k16.row.col.f32.bf16.bf16.f32 "      \
        "{%0,%1,%2,%3}, {%4,%5,%6,%7}, {%8,%9}, {%0,%1,%2,%3};"              \
        : "+f"((c)[0]), "+f"((c)[1]), "+f"((c)[2]), "+f"((c)[3])             \
        : "r"(A0), "r"(A1), "r"(A2), "r"(A3), "r"(B0), "r"(B1))

__global__ __launch_bounds__(256)
void k_mma(const __nv_bfloat16* __restrict__ Ah, const __nv_bfloat16* __restrict__ Al,
           const __nv_bfloat16* __restrict__ Bh, const __nv_bfloat16* __restrict__ Bl,
           int N, const float* __restrict__ bias1, const float* __restrict__ bias2,
           float* __restrict__ C)
{
    extern __shared__ char dsm[];
    char* sAh = dsm;
    char* sAl = dsm + 16384;
    char* sBh = dsm + 32768;
    char* sBl = dsm + 49152;
    const uint32_t uAh = smem_u32(sAh), uAl = smem_u32(sAl);
    const uint32_t uBh = smem_u32(sBh), uBl = smem_u32(sBl);

    const int tid = threadIdx.x, lane = tid & 31, wid = tid >> 5;
    const int bm = blockIdx.y, bn = blockIdx.x;
    const int wm = (wid >> 2) * 64, wn = (wid & 3) * 32;

    // per-lane ldmatrix addressing components
    const int aRow = lane & 15, aGrp = lane >> 4;
    const int bRow = (lane & 7) + ((lane >> 4) << 3), bGrp = (lane >> 3) & 1;

    float acc[4][4][4];
#pragma unroll
    for (int i = 0; i < 4; i++)
#pragma unroll
        for (int j = 0; j < 4; j++)
#pragma unroll
            for (int q = 0; q < 4; q++) acc[i][j][q] = 0.f;

    for (int c = 0; c < 8; ++c) {
        if (c) __syncthreads();   // previous chunk's compute done
#pragma unroll
        for (int i = 0; i < 4; ++i) {
            int idx = i * 256 + tid;
            int row = idx >> 3, grp = idx & 7;
            uint32_t so = (uint32_t)(row * 128 + ((grp ^ (row & 7)) << 4));
            size_t ga = ((size_t)(bm * 128 + row) * 512 + c * 64 + grp * 8) * 2;
            size_t gb = ((size_t)(bn * 128 + row) * 512 + c * 64 + grp * 8) * 2;
            *(uint4*)(sAh + so) = *(const uint4*)((const char*)Ah + ga);
            *(uint4*)(sAl + so) = *(const uint4*)((const char*)Al + ga);
            *(uint4*)(sBh + so) = *(const uint4*)((const char*)Bh + gb);
            *(uint4*)(sBl + so) = *(const uint4*)((const char*)Bl + gb);
        }
        __syncthreads();

#pragma unroll
        for (int ks = 0; ks < 4; ++ks) {
            uint32_t bh[8], bl[8];
#pragma unroll
            for (int h = 0; h < 2; ++h) {
                int row = wn + h * 16 + bRow;
                int grp = 2 * ks + bGrp;
                uint32_t off = (uint32_t)(row * 128 + ((grp ^ (row & 7)) << 4));
                LDSM4(bh[h*4+0], bh[h*4+1], bh[h*4+2], bh[h*4+3], uBh + off);
                LDSM4(bl[h*4+0], bl[h*4+1], bl[h*4+2], bl[h*4+3], uBl + off);
            }
#pragma unroll
            for (int mi = 0; mi < 4; ++mi) {
                int row = wm + mi * 16 + aRow;
                int grp = 2 * ks + aGrp;
                uint32_t off = (uint32_t)(row * 128 + ((grp ^ (row & 7)) << 4));
                uint32_t ah[4], al[4];
                LDSM4(ah[0], ah[1], ah[2], ah[3], uAh + off);
                LDSM4(al[0], al[1], al[2], al[3], uAl + off);
#pragma unroll
                for (int ni = 0; ni < 4; ++ni) {
                    int bx = (ni >> 1) * 4 + (ni & 1) * 2;
                    MMA16816(acc[mi][ni], ah[0], ah[1], ah[2], ah[3], bh[bx], bh[bx+1]);
                    MMA16816(acc[mi][ni], ah[0], ah[1], ah[2], ah[3], bl[bx], bl[bx+1]);
                    MMA16816(acc[mi][ni], al[0], al[1], al[2], al[3], bh[bx], bh[bx+1]);
                }
            }
        }
    }

    // epilogue: direct global stores (float2, 32B-sector coalesced per quad)
#pragma unroll
    for (int mi = 0; mi < 4; ++mi) {
#pragma unroll
        for (int ni = 0; ni < 4; ++ni) {
            int row = bm * 128 + wm + mi * 16 + (lane >> 2);
            int col = bn * 128 + wn + ni * 8 + ((lane & 3) << 1);
            float b0 = bias1[col]     + (bias2 ? bias2[col]     : 0.f);
            float b1 = bias1[col + 1] + (bias2 ? bias2[col + 1] : 0.f);
            float* p0 = &C[(size_t)row * N + col];
            float* p1 = &C[(size_t)(row + 8) * N + col];
            float2 v0 = make_float2(acc[mi][ni][0] + b0, acc[mi][ni][1] + b1);
            float2 v1 = make_float2(acc[mi][ni][2] + b0, acc[mi][ni][3] + b1);
            *(float2*)p0 = v0;
            *(float2*)p1 = v1;
        }
    }
}

// ---------------- generic fp32 SGEMM (small GEMMs: K3, K6) ----------------
__global__ __launch_bounds__(256)
void k_sgemm(const float* __restrict__ A1, const float* __restrict__ A2,
             int ksplit, int K, int N,
             const float* __restrict__ Bw,
             const float* __restrict__ bias1, const float* __restrict__ bias2,
             float* __restrict__ C, int act)
{
    __shared__ float As[16][132];
    __shared__ float Bs[16][132];
    const int tid = threadIdx.x;
    const int bm = blockIdx.y, bn = blockIdx.x;
    const int lrow = tid >> 2;
    const int lk4  = (tid & 3) << 2;
    const int tx = tid & 15, ty = tid >> 4;

    float acc[8][8];
#pragma unroll
    for (int i = 0; i < 8; i++)
#pragma unroll
        for (int j = 0; j < 8; j++) acc[i][j] = 0.f;

    for (int kt = 0; kt < K; kt += 16) {
        const float* Ab; int lda, kof;
        if (kt < ksplit) { Ab = A1; lda = ksplit;     kof = kt; }
        else             { Ab = A2; lda = K - ksplit; kof = kt - ksplit; }
#pragma unroll
        for (int rr = 0; rr < 128; rr += 64) {
            int row = lrow + rr;
            float4 va = *(const float4*)(Ab + (size_t)(bm * 128 + row) * lda + kof + lk4);
            As[lk4 + 0][row] = va.x; As[lk4 + 1][row] = va.y;
            As[lk4 + 2][row] = va.z; As[lk4 + 3][row] = va.w;
            int nrow = bn * 128 + row;
            float4 vb = make_float4(0.f, 0.f, 0.f, 0.f);
            if (nrow < N) vb = *(const float4*)(Bw + (size_t)nrow * K + kt + lk4);
            Bs[lk4 + 0][row] = vb.x; Bs[lk4 + 1][row] = vb.y;
            Bs[lk4 + 2][row] = vb.z; Bs[lk4 + 3][row] = vb.w;
        }
        __syncthreads();
#pragma unroll
        for (int k = 0; k < 16; ++k) {
            float4 a0 = *(const float4*)&As[k][ty * 8];
            float4 a1 = *(const float4*)&As[k][ty * 8 + 4];
            float4 b0 = *(const float4*)&Bs[k][tx * 8];
            float4 b1 = *(const float4*)&Bs[k][tx * 8 + 4];
            float av[8] = {a0.x, a0.y, a0.z, a0.w, a1.x, a1.y, a1.z, a1.w};
            float bv[8] = {b0.x, b0.y, b0.z, b0.w, b1.x, b1.y, b1.z, b1.w};
#pragma unroll
            for (int i = 0; i < 8; i++)
#pragma unroll
                for (int j = 0; j < 8; j++)
                    acc[i][j] = fmaf(av[i], bv[j], acc[i][j]);
        }
        __syncthreads();
    }

#pragma unroll
    for (int i = 0; i < 8; i++) {
        int m = bm * 128 + ty * 8 + i;
#pragma unroll
        for (int j = 0; j < 8; j++) {
            int n = bn * 128 + tx * 8 + j;
            if (n < N) {
                float v = acc[i][j] + bias1[n] + (bias2 ? bias2[n] : 0.f);
                if (act) v = tanhf(v);
                C[(size_t)m * N + n] = v;
            }
        }
    }
}

// ---------------- LSTM-1 persistent kernel ----------------
__global__ __launch_bounds__(256)
void k_lstm1(const float* __restrict__ Whh)
{
    __shared__ float wsm[16][512];
    __shared__ float hsm[2048];
    __shared__ float gsum[64];
    __shared__ float csm[16];
    const int tid  = threadIdx.x;
    const int u0   = blockIdx.x * 4;
    const int warp = tid >> 5, lane = tid & 31;

    for (int i = tid; i < 16 * 512; i += 256) {
        int r = i >> 9, k = i & 511;
        wsm[r][k] = Whh[(size_t)((r >> 2) * 512 + u0 + (r & 3)) * 512 + k];
    }
    if (tid < 16) csm[tid] = 0.f;
    unsigned base = 0;
    if (tid == 0) base = *(volatile unsigned*)&g_bar_phase;
    __syncthreads();

    for (int t = 0; t < T_; ++t) {
        float xg[4];
        if (tid < 16) {
            int uu = tid >> 2, b = tid & 3;
            const float* xr = g_xw + (size_t)(b * T_ + t) * 2048 + u0 + uu;
            xg[0] = xr[0]; xg[1] = xr[512]; xg[2] = xr[1024]; xg[3] = xr[1536];
        }
        if (t > 0) {
            for (int i = tid; i < 512; i += 256) {
                int b = i >> 7, k4 = i & 127;
                ((float4*)hsm)[i] =
                    ((const float4*)(g_enc + (size_t)(b * T_ + t - 1) * 512))[k4];
            }
        } else {
            for (int i = tid; i < 2048; i += 256) hsm[i] = 0.f;
        }
        __syncthreads();

#pragma unroll
        for (int s = 0; s < 8; ++s) {
            int task = warp * 8 + s;
            int r = task >> 2, b = task & 3;
            const float4* wv = (const float4*)wsm[r];
            const float4* hv = (const float4*)(hsm + b * 512);
            float sum = 0.f;
#pragma unroll
            for (int q = 0; q < 4; ++q) {
                float4 w4 = wv[q * 32 + lane];
                float4 h4 = hv[q * 32 + lane];
                sum = fmaf(w4.x, h4.x, fmaf(w4.y, h4.y,
                      fmaf(w4.z, h4.z, fmaf(w4.w, h4.w, sum))));
            }
            sum += __shfl_down_sync(0xffffffffu, sum, 16);
            sum += __shfl_down_sync(0xffffffffu, sum, 8);
            sum += __shfl_down_sync(0xffffffffu, sum, 4);
            sum += __shfl_down_sync(0xffffffffu, sum, 2);
            sum += __shfl_down_sync(0xffffffffu, sum, 1);
            if (lane == 0) gsum[task] = sum;
        }
        __syncthreads();

        if (tid < 16) {
            int uu = tid >> 2, b = tid & 3;
            float gi = gsum[((0 * 4 + uu) << 2) | b] + xg[0];
            float gf = gsum[((1 * 4 + uu) << 2) | b] + xg[1];
            float gg = gsum[((2 * 4 + uu) << 2) | b] + xg[2];
            float go = gsum[((3 * 4 + uu) << 2) | b] + xg[3];
            float c = sigf(gf) * csm[tid] + sigf(gi) * tanhf(gg);
            csm[tid] = c;
            float h = sigf(go) * tanhf(c);
            g_enc[(size_t)(b * T_ + t) * 512 + u0 + uu] = h;
            __threadfence();
        }
        __syncthreads();

        if (tid == 0) {
            unsigned a = atomicAdd(&g_bar_cnt, 1u);
            if (a == NB1 - 1) {
                atomicExch(&g_bar_cnt, 0u);
                __threadfence();
                atomicAdd(&g_bar_phase, 1u);
            } else {
                while ((*(volatile unsigned*)&g_bar_phase) - base < (unsigned)(t + 1)) { }
            }
        }
        __syncthreads();
    }
}

// ---------------- LSTM-2 (P=20) + mu/sigma scan ----------------
__global__ __launch_bounds__(128)
void k_lstm2(const float* __restrict__ Wp_hh,
             const float* __restrict__ Wmu, const float* __restrict__ bmu,
             const float* __restrict__ Wsig, const float* __restrict__ bsig,
             const int* __restrict__ pad)
{
    __shared__ float wp[80][20];
    __shared__ float hp[4][20];
    __shared__ float cp[4][20];
    __shared__ float gp[4][80];
    __shared__ float wmu_s[3][20];
    __shared__ float wsig_s[20];
    __shared__ float mu_prev[4];
    __shared__ float invL[4];
    const int tid = threadIdx.x;

    for (int i = tid; i < 1600; i += 128) wp[i / 20][i % 20] = Wp_hh[i];
    for (int i = tid; i < 60; i += 128) wmu_s[i / 20][i % 20] = Wmu[i];
    if (tid < 20) wsig_s[tid] = Wsig[tid];
    if (tid < 80) { hp[tid / 20][tid % 20] = 0.f; cp[tid / 20][tid % 20] = 0.f; }
    if (tid < 4)  { mu_prev[tid] = 0.f; invL[tid] = 1.f / (float)pad[tid]; }
    __syncthreads();

    for (int t = 0; t < T_; ++t) {
        for (int i = tid; i < 320; i += 128) {
            int b = i / 80, r = i % 80;
            float s = g_pxw[(size_t)(b * T_ + t) * 80 + r];
#pragma unroll
            for (int k = 0; k < 20; ++k) s = fmaf(wp[r][k], hp[b][k], s);
            gp[b][r] = s;
        }
        __syncthreads();
        if (tid < 80) {
            int b = tid / 20, u = tid % 20;
            float c = sigf(gp[b][20 + u]) * cp[b][u] + sigf(gp[b][u]) * tanhf(gp[b][40 + u]);
            cp[b][u] = c;
            hp[b][u] = sigf(gp[b][60 + u]) * tanhf(c);
        }
        __syncthreads();
        if (tid < 4) {
            int b = tid;
            float m0 = bmu[0], m1 = bmu[1], m2 = bmu[2], sg = bsig[0];
#pragma unroll
            for (int k = 0; k < 20; ++k) {
                float h = hp[b][k];
                m0 = fmaf(wmu_s[0][k], h, m0);
                m1 = fmaf(wmu_s[1][k], h, m1);
                m2 = fmaf(wmu_s[2][k], h, m2);
                sg = fmaf(wsig_s[k], h, sg);
            }
            m0 = fmaxf(m0, 0.f); m1 = fmaxf(m1, 0.f); m2 = fmaxf(m2, 0.f);
            sg = sigf(sg);
            float base_ = (m1 + m2 * (float)(t + 1)) * invL[b];
            float mu = fmaf(m0, mu_prev[b], base_);
            mu_prev[b] = mu;
            g_mu[b * T_ + t]  = mu;
            g_sig[b * T_ + t] = sg;
        }
        __syncthreads();
    }
}

// ---------------- attention weights + context ----------------
__global__ __launch_bounds__(256)
void k_attn()
{
    __shared__ float wsm[1024];
    __shared__ float red[256];
    const int tid = threadIdx.x;
    const int bj = blockIdx.x;
    const int b = bj >> 10, j = bj & 1023;
    const float mu = g_mu[bj];
    const float sg = g_sig[bj];
    const float invd  = 1.f / (2.f * sg * sg + 0.001f);
    const float invj1 = 1.f / (float)(j + 1);

    float lsum = 0.f;
    for (int t = tid; t < 1024; t += 256) {
        float w = 0.f;
        if (t <= j) {
            float r = (float)t * invj1 - mu;
            w = expf(-r * r * invd);
        }
        wsm[t] = w;
        lsum += w;
    }
    red[tid] = lsum;
    __syncthreads();
    for (int s = 128; s > 0; s >>= 1) {
        if (tid < s) red[tid] += red[tid + s];
        __syncthreads();
    }
    const float scale = 1.f / fmaxf(red[0], 1e-12f);

    const float2* encb = (const float2*)(g_enc + (size_t)b * T_ * 512);
    float2 acc = make_float2(0.f, 0.f);
#pragma unroll 4
    for (int t = 0; t <= j; ++t) {
        float w = wsm[t];
        float2 e = encb[t * 256 + tid];
        acc.x = fmaf(w, e.x, acc.x);
        acc.y = fmaf(w, e.y, acc.y);
    }
    acc.x *= scale; acc.y *= scale;
    ((float2*)g_ctx)[(size_t)bj * 256 + tid] = acc;
}

// ---------------- launch ----------------
extern "C" void kernel_launch(void* const* d_in, const int* in_sizes, int n_in,
                              void* d_out, int out_size)
{
    const int*   ids      = (const int*)d_in[0];
    const int*   pad      = (const int*)d_in[1];
    const float* emb      = (const float*)d_in[2];
    const float* dec_bias = (const float*)d_in[3];
    const float* Wih      = (const float*)d_in[4];
    const float* Whh      = (const float*)d_in[5];
    const float* bih      = (const float*)d_in[6];
    const float* bhh      = (const float*)d_in[7];
    const float* Wp_ih    = (const float*)d_in[8];
    const float* Wp_hh    = (const float*)d_in[9];
    const float* bp_ih    = (const float*)d_in[10];
    const float* bp_hh    = (const float*)d_in[11];
    const float* Wmu      = (const float*)d_in[12];
    const float* bmu      = (const float*)d_in[13];
    const float* Wsig     = (const float*)d_in[14];
    const float* bsig     = (const float*)d_in[15];
    const float* Wc       = (const float*)d_in[16];
    const float* bc       = (const float*)d_in[17];
    float* out = (float*)d_out;

    float *p_xw, *p_enc, *p_pxw, *p_ctx, *p_comb;
    __nv_bfloat16 *p_ehi, *p_elo, *p_whi, *p_wlo, *p_xhi, *p_xlo, *p_chi, *p_clo;
    cudaGetSymbolAddress((void**)&p_xw,   g_xw);
    cudaGetSymbolAddress((void**)&p_enc,  g_enc);
    cudaGetSymbolAddress((void**)&p_pxw,  g_pxw);
    cudaGetSymbolAddress((void**)&p_ctx,  g_ctx);
    cudaGetSymbolAddress((void**)&p_comb, g_comb);
    cudaGetSymbolAddress((void**)&p_ehi,  g_emb_hi);
    cudaGetSymbolAddress((void**)&p_elo,  g_emb_lo);
    cudaGetSymbolAddress((void**)&p_whi,  g_wih_hi);
    cudaGetSymbolAddress((void**)&p_wlo,  g_wih_lo);
    cudaGetSymbolAddress((void**)&p_xhi,  g_x_hi);
    cudaGetSymbolAddress((void**)&p_xlo,  g_x_lo);
    cudaGetSymbolAddress((void**)&p_chi,  g_comb_hi);
    cudaGetSymbolAddress((void**)&p_clo,  g_comb_lo);

    cudaFuncSetAttribute(k_mma, cudaFuncAttributeMaxDynamicSharedMemorySize, MMA_SMEM);

    // splits for bf16 GEMMs
    k_split<<<(V_ * H_ + 255) / 256, 256>>>(emb, p_ehi, p_elo, V_ * H_);
    k_split<<<(4 * H_ * H_ + 255) / 256, 256>>>(Wih, p_whi, p_wlo, 4 * H_ * H_);
    // embedding gather (bf16 hi/lo)
    k_embed_bf<<<(BT * H_ + 255) / 256, 256>>>(ids);
    // K1: xw = x @ Wih^T + bih + bhh  -> [4096, 2048]  (mma.sync bf16x3)
    k_mma<<<dim3(2048 / 128, BT / 128), 256, MMA_SMEM>>>(
        p_xhi, p_xlo, p_whi, p_wlo, 2048, bih, bhh, p_xw);
    // K2: LSTM-1 recurrence -> enc
    k_lstm1<<<NB1, 256>>>(Whh);
    // K3: pxw = enc @ Wp_ih^T + bp_ih + bp_hh -> [4096, 80]
    k_sgemm<<<dim3(1, BT / 128), 256>>>(p_enc, nullptr, 512, 512, 80,
                                        Wp_ih, bp_ih, bp_hh, p_pxw, 0);
    // K4: LSTM-2 + mu/sigma scan
    k_lstm2<<<1, 128>>>(Wp_hh, Wmu, bmu, Wsig, bsig, pad);
    // K5: attention + context
    k_attn<<<BT, 256>>>();
    // K6: combined = tanh([ctx, enc] @ Wc^T + bc) -> [4096, 512]
    k_sgemm<<<dim3(512 / 128, BT / 128), 256>>>(p_ctx, p_enc, 512, 1024, 512,
                                                Wc, bc, nullptr, p_comb, 1);
    // split combined for decoder
    k_split<<<(BT * H_ + 255) / 256, 256>>>(p_comb, p_chi, p_clo, BT * H_);
    // K7: logits = combined @ emb^T + dec_bias -> [4096, 32000]  (mma.sync bf16x3)
    k_mma<<<dim3(V_ / 128, BT / 128), 256, MMA_SMEM>>>(
        p_chi, p_clo, p_ehi, p_elo, V_, dec_bias, nullptr, out);
}

// round 6
// speedup vs baseline: 1.8964x; 1.5479x over previous
#include <cuda_runtime.h>
#include <cuda_bf16.h>
#include <cstdint>
#include <math.h>

#define B_ 4
#define T_ 1024
#define H_ 512
#define P_ 20
#define V_ 32000
#define BT (B_*T_)
#define NB1 128

typedef __nv_bfloat16 bf16;

// ---------------- scratch (device globals; zero-initialized at load) ----------------
__device__ __align__(256) float g_xw[BT*2048];
__device__ __align__(256) float g_enc[BT*512];
__device__ __align__(256) float g_pxw[BT*128];     // padded N=128 (80 used)
__device__ float g_mu[BT];
__device__ float g_sig[BT];
__device__ unsigned g_cnt[256];                    // 8 groups, stride 32
__device__ unsigned g_root;
__device__ float g_bp[128];                        // padded bias for pxw

__device__ __align__(256) bf16 g_emb_hi[V_*H_];
__device__ __align__(256) bf16 g_emb_lo[V_*H_];
__device__ __align__(256) bf16 g_wih_hi[4*H_*H_];
__device__ __align__(256) bf16 g_wih_lo[4*H_*H_];
__device__ __align__(256) bf16 g_x_hi[BT*H_];
__device__ __align__(256) bf16 g_x_lo[BT*H_];
__device__ __align__(256) bf16 g_enc_hi[BT*H_];    // row-major [bt][h]
__device__ __align__(256) bf16 g_enc_lo[BT*H_];
__device__ __align__(256) bf16 g_et_hi[B_*H_*T_];  // transposed [b][h][t]
__device__ __align__(256) bf16 g_et_lo[B_*H_*T_];
__device__ __align__(256) bf16 g_w_hi[B_*T_*T_];   // attention weights [b][j][t]
__device__ __align__(256) bf16 g_w_lo[B_*T_*T_];
__device__ __align__(256) bf16 g_ctx_hi[BT*H_];
__device__ __align__(256) bf16 g_ctx_lo[BT*H_];
__device__ __align__(256) bf16 g_comb_hi[BT*H_];
__device__ __align__(256) bf16 g_comb_lo[BT*H_];
__device__ __align__(256) bf16 g_wc_hi[H_*2*H_];
__device__ __align__(256) bf16 g_wc_lo[H_*2*H_];
__device__ __align__(256) bf16 g_wp_hi[128*H_];    // padded rows 80..127 stay zero
__device__ __align__(256) bf16 g_wp_lo[128*H_];

__device__ __forceinline__ float sigf(float x) { return 1.f / (1.f + __expf(-x)); }
__device__ __forceinline__ float tfast(float x) {
    float a = fabsf(x);
    float e = __expf(2.f * a);
    float t = 1.f - 2.f / (1.f + e);
    return copysignf(t, x);
}

__device__ __forceinline__ uint32_t smem_u32(const void* p) {
    uint32_t a;
    asm("{ .reg .u64 t; cvta.to.shared.u64 t, %1; cvt.u32.u64 %0, t; }"
        : "=r"(a) : "l"(p));
    return a;
}

#define CP_ASYNC16(s, g) \
    asm volatile("cp.async.cg.shared.global [%0], [%1], 16;" :: "r"(s), "l"(g))
#define CP_COMMIT() asm volatile("cp.async.commit_group;" ::: "memory")
#define CP_WAIT1()  asm volatile("cp.async.wait_group 1;" ::: "memory")
#define CP_WAIT0()  asm volatile("cp.async.wait_group 0;" ::: "memory")

#define LDSM4(r0, r1, r2, r3, a)                                             \
    asm volatile("ldmatrix.sync.aligned.m8n8.x4.shared.b16 {%0,%1,%2,%3}, [%4];" \
        : "=r"(r0), "=r"(r1), "=r"(r2), "=r"(r3) : "r"(a))

#define MMA16816(c, A0, A1, A2, A3, B0, B1)                                  \
    asm volatile("mma.sync.aligned.m16n8k16.row.col.f32.bf16.bf16.f32 "      \
        "{%0,%1,%2,%3}, {%4,%5,%6,%7}, {%8,%9}, {%0,%1,%2,%3};"              \
        : "+f"((c)[0]), "+f"((c)[1]), "+f"((c)[2]), "+f"((c)[3])             \
        : "r"(A0), "r"(A1), "r"(A2), "r"(A3), "r"(B0), "r"(B1))

// ---------------- split fp32 -> bf16 hi/lo ----------------
__global__ void k_split(const float* __restrict__ src,
                        bf16* __restrict__ hi, bf16* __restrict__ lo, int n)
{
    int i = blockIdx.x * blockDim.x + threadIdx.x;
    if (i < n) {
        float v = src[i];
        bf16 h = __float2bfloat16(v);
        hi[i] = h;
        lo[i] = __float2bfloat16(v - __bfloat162float(h));
    }
}

__global__ void k_padbias(const float* __restrict__ b1, const float* __restrict__ b2)
{
    int i = threadIdx.x;
    if (i < 80) g_bp[i] = b1[i] + b2[i];
}

// ---------------- embedding gather (bf16 hi/lo) + barrier counter reset ----------------
__global__ void k_embed_bf(const int* __restrict__ ids)
{
    if (blockIdx.x == 0) {
        if (threadIdx.x == 0) g_root = 0;
        if (threadIdx.x < 8) g_cnt[threadIdx.x * 32] = 0;
    }
    int i = blockIdx.x * blockDim.x + threadIdx.x;
    if (i < BT * H_) {
        int bt = i >> 9;
        int h  = i & 511;
        size_t src = (size_t)ids[bt] * H_ + h;
        g_x_hi[i] = g_emb_hi[src];
        g_x_lo[i] = g_emb_lo[src];
    }
}

// ---------------- generalized bf16x3 HMMA GEMM, cp.async double-buffered ----------------
// C[m,n] = sum_k A(m,k)*B(n,k) (+bias) ; A split at ksplit chunks (64 k per chunk)
// optional m-batching: bq = bm / mbpb selects batch; A1/B advance by batch strides.
#define MMA_SMEM (2 * 65536)

__global__ __launch_bounds__(256)
void k_mma(const bf16* __restrict__ Ah1, const bf16* __restrict__ Al1, int lda1,
           const bf16* __restrict__ Ah2, const bf16* __restrict__ Al2, int lda2,
           int ksplit, int nchunks, int mbpb, size_t sAbat,
           const bf16* __restrict__ Bh, const bf16* __restrict__ Bl, int ldb, size_t sBbat,
           int N, const float* __restrict__ bias1, const float* __restrict__ bias2,
           float* __restrict__ Cf, bf16* __restrict__ Chi, bf16* __restrict__ Clo,
           int actTanh)
{
    extern __shared__ char dsm[];
    const uint32_t ub = smem_u32(dsm);
    const int tid = threadIdx.x, lane = tid & 31, wid = tid >> 5;
    const int bm = blockIdx.y, bn = blockIdx.x;
    const int bq = bm / mbpb;
    const int am0 = (bm - bq * mbpb) * 128;
    const bf16* A1h = Ah1 + (size_t)bq * sAbat;
    const bf16* A1l = Al1 + (size_t)bq * sAbat;
    const bf16* Bbh = Bh + (size_t)bq * sBbat;
    const bf16* Bbl = Bl + (size_t)bq * sBbat;

    const int wm = (wid >> 2) * 64, wn = (wid & 3) * 32;
    const int aRow = lane & 15, aGrp = lane >> 4;
    const int bRow = (lane & 7) + ((lane >> 4) << 3), bGrp = (lane >> 3) & 1;

    auto issue = [&](int c, int st) {
        uint32_t sb = ub + st * 65536;
#pragma unroll
        for (int i = 0; i < 4; ++i) {
            int idx = i * 256 + tid;
            int row = idx >> 3, seg = idx & 7;
            uint32_t so = sb + (uint32_t)(row * 128 + ((seg ^ (row & 7)) << 4));
            const bf16 *pah, *pal;
            if (c < ksplit) {
                size_t o = (size_t)(am0 + row) * lda1 + c * 64 + seg * 8;
                pah = A1h + o; pal = A1l + o;
            } else {
                size_t o = (size_t)(am0 + row) * lda2 + (c - ksplit) * 64 + seg * 8;
                pah = Ah2 + o; pal = Al2 + o;
            }
            size_t ob = (size_t)(bn * 128 + row) * ldb + c * 64 + seg * 8;
            CP_ASYNC16(so,         pah);
            CP_ASYNC16(so + 16384, pal);
            CP_ASYNC16(so + 32768, Bbh + ob);
            CP_ASYNC16(so + 49152, Bbl + ob);
        }
        CP_COMMIT();
    };

    float acc[4][4][4];
#pragma unroll
    for (int i = 0; i < 4; i++)
#pragma unroll
        for (int j = 0; j < 4; j++)
#pragma unroll
            for (int q = 0; q < 4; q++) acc[i][j][q] = 0.f;

    issue(0, 0);
    for (int c = 0; c < nchunks; ++c) {
        if (c + 1 < nchunks) { issue(c + 1, (c + 1) & 1); CP_WAIT1(); }
        else CP_WAIT0();
        __syncthreads();

        uint32_t uAh = ub + (c & 1) * 65536;
        uint32_t uAl = uAh + 16384, uBh = uAh + 32768, uBl = uAh + 49152;
#pragma unroll
        for (int ks = 0; ks < 4; ++ks) {
            uint32_t bh[8], bl[8];
#pragma unroll
            for (int h = 0; h < 2; ++h) {
                int row = wn + h * 16 + bRow;
                int grp = 2 * ks + bGrp;
                uint32_t off = (uint32_t)(row * 128 + ((grp ^ (row & 7)) << 4));
                LDSM4(bh[h*4+0], bh[h*4+1], bh[h*4+2], bh[h*4+3], uBh + off);
                LDSM4(bl[h*4+0], bl[h*4+1], bl[h*4+2], bl[h*4+3], uBl + off);
            }
#pragma unroll
            for (int mi = 0; mi < 4; ++mi) {
                int row = wm + mi * 16 + aRow;
                int grp = 2 * ks + aGrp;
                uint32_t off = (uint32_t)(row * 128 + ((grp ^ (row & 7)) << 4));
                uint32_t ah[4], al[4];
                LDSM4(ah[0], ah[1], ah[2], ah[3], uAh + off);
                LDSM4(al[0], al[1], al[2], al[3], uAl + off);
#pragma unroll
                for (int ni = 0; ni < 4; ++ni) {
                    int bx = (ni >> 1) * 4 + (ni & 1) * 2;
                    MMA16816(acc[mi][ni], ah[0], ah[1], ah[2], ah[3], bh[bx], bh[bx+1]);
                    MMA16816(acc[mi][ni], ah[0], ah[1], ah[2], ah[3], bl[bx], bl[bx+1]);
                    MMA16816(acc[mi][ni], al[0], al[1], al[2], al[3], bh[bx], bh[bx+1]);
                }
            }
        }
        __syncthreads();
    }

    // epilogue
#pragma unroll
    for (int mi = 0; mi < 4; ++mi) {
#pragma unroll
        for (int ni = 0; ni < 4; ++ni) {
            int row = bm * 128 + wm + mi * 16 + (lane >> 2);
            int col = bn * 128 + wn + ni * 8 + ((lane & 3) << 1);
            float b0 = 0.f, b1 = 0.f;
            if (bias1) { b0 = bias1[col]; b1 = bias1[col + 1]; }
            if (bias2) { b0 += bias2[col]; b1 += bias2[col + 1]; }
            float v00 = acc[mi][ni][0] + b0, v01 = acc[mi][ni][1] + b1;
            float v10 = acc[mi][ni][2] + b0, v11 = acc[mi][ni][3] + b1;
            if (actTanh) {
                v00 = tfast(v00); v01 = tfast(v01);
                v10 = tfast(v10); v11 = tfast(v11);
            }
            size_t i0 = (size_t)row * N + col;
            size_t i1 = (size_t)(row + 8) * N + col;
            if (Cf) {
                *(float2*)&Cf[i0] = make_float2(v00, v01);
                *(float2*)&Cf[i1] = make_float2(v10, v11);
            }
            if (Chi) {
                bf16 h00 = __float2bfloat16(v00), h01 = __float2bfloat16(v01);
                bf16 h10 = __float2bfloat16(v10), h11 = __float2bfloat16(v11);
                __nv_bfloat162 p;
                p.x = h00; p.y = h01; *(__nv_bfloat162*)&Chi[i0] = p;
                p.x = h10; p.y = h11; *(__nv_bfloat162*)&Chi[i1] = p;
                p.x = __float2bfloat16(v00 - __bfloat162float(h00));
                p.y = __float2bfloat16(v01 - __bfloat162float(h01));
                *(__nv_bfloat162*)&Clo[i0] = p;
                p.x = __float2bfloat16(v10 - __bfloat162float(h10));
                p.y = __float2bfloat16(v11 - __bfloat162float(h11));
                *(__nv_bfloat162*)&Clo[i1] = p;
            }
        }
    }
}

// ---------------- LSTM-1 persistent kernel (register weights, 2-level barrier) -------
__global__ __launch_bounds__(256)
void k_lstm1(const float* __restrict__ Whh)
{
    __shared__ float hsm[2048];
    __shared__ float gsum[64];
    __shared__ float csm[16];
    const int tid  = threadIdx.x;
    const int u0   = blockIdx.x * 4;
    const int warp = tid >> 5, lane = tid & 31;
    const int grp  = blockIdx.x >> 4;

    // register-resident weight rows: warp owns r0=2w, r1=2w+1 (r = gate*4+uu)
    const int r0 = 2 * warp, r1 = 2 * warp + 1;
    const float* W0 = Whh + ((size_t)((r0 >> 2) * 512 + u0 + (r0 & 3))) * 512;
    const float* W1 = Whh + ((size_t)((r1 >> 2) * 512 + u0 + (r1 & 3))) * 512;
    float4 w0[4], w1[4];
#pragma unroll
    for (int q = 0; q < 4; ++q) {
        w0[q] = *(const float4*)(W0 + 4 * lane + 128 * q);
        w1[q] = *(const float4*)(W1 + 4 * lane + 128 * q);
    }
    if (tid < 16) csm[tid] = 0.f;
    __syncthreads();

    for (int t = 0; t < T_; ++t) {
        float xg[4];
        if (tid < 16) {
            int uu = tid >> 2, b = tid & 3;
            const float* xr = g_xw + (size_t)(b * T_ + t) * 2048 + u0 + uu;
            xg[0] = xr[0]; xg[1] = xr[512]; xg[2] = xr[1024]; xg[3] = xr[1536];
        }
        if (t > 0) {
            for (int i = tid; i < 512; i += 256) {
                int b = i >> 7, k4 = i & 127;
                ((float4*)hsm)[i] =
                    ((const float4*)(g_enc + (size_t)(b * T_ + t - 1) * 512))[k4];
            }
        } else {
            for (int i = tid; i < 2048; i += 256) hsm[i] = 0.f;
        }
        __syncthreads();

        float s[8];
#pragma unroll
        for (int b = 0; b < 4; ++b) {
            const float* hb = hsm + b * 512 + 4 * lane;
            float4 h0 = *(const float4*)(hb);
            float4 h1 = *(const float4*)(hb + 128);
            float4 h2 = *(const float4*)(hb + 256);
            float4 h3 = *(const float4*)(hb + 384);
            float a0, a1;
            a0 = w0[0].x*h0.x + w0[0].y*h0.y + w0[0].z*h0.z + w0[0].w*h0.w;
            a0 += w0[1].x*h1.x + w0[1].y*h1.y + w0[1].z*h1.z + w0[1].w*h1.w;
            a0 += w0[2].x*h2.x + w0[2].y*h2.y + w0[2].z*h2.z + w0[2].w*h2.w;
            a0 += w0[3].x*h3.x + w0[3].y*h3.y + w0[3].z*h3.z + w0[3].w*h3.w;
            a1 = w1[0].x*h0.x + w1[0].y*h0.y + w1[0].z*h0.z + w1[0].w*h0.w;
            a1 += w1[1].x*h1.x + w1[1].y*h1.y + w1[1].z*h1.z + w1[1].w*h1.w;
            a1 += w1[2].x*h2.x + w1[2].y*h2.y + w1[2].z*h2.z + w1[2].w*h2.w;
            a1 += w1[3].x*h3.x + w1[3].y*h3.y + w1[3].z*h3.z + w1[3].w*h3.w;
            s[b * 2] = a0; s[b * 2 + 1] = a1;
        }
#pragma unroll
        for (int i = 0; i < 8; ++i) {
            s[i] += __shfl_xor_sync(0xffffffffu, s[i], 16);
            s[i] += __shfl_xor_sync(0xffffffffu, s[i], 8);
            s[i] += __shfl_xor_sync(0xffffffffu, s[i], 4);
            s[i] += __shfl_xor_sync(0xffffffffu, s[i], 2);
            s[i] += __shfl_xor_sync(0xffffffffu, s[i], 1);
        }
        if (lane < 8) {
            float v = (lane < 4) ? s[2 * lane] : s[2 * (lane - 4) + 1];
            gsum[warp * 8 + lane] = v;
        }
        __syncthreads();

        if (tid < 16) {
            int uu = tid >> 2, b = tid & 3;
            float gi = gsum[((0 * 4 + uu) << 2) | b] + xg[0];
            float gf = gsum[((1 * 4 + uu) << 2) | b] + xg[1];
            float gg = gsum[((2 * 4 + uu) << 2) | b] + xg[2];
            float go = gsum[((3 * 4 + uu) << 2) | b] + xg[3];
            float c = sigf(gf) * csm[tid] + sigf(gi) * tfast(gg);
            csm[tid] = c;
            float h = sigf(go) * tfast(c);
            int u  = u0 + uu;
            size_t bt = (size_t)(b * T_ + t);
            g_enc[bt * 512 + u] = h;
            bf16 hh = __float2bfloat16(h);
            bf16 hl = __float2bfloat16(h - __bfloat162float(hh));
            g_enc_hi[bt * 512 + u] = hh;
            g_enc_lo[bt * 512 + u] = hl;
            size_t ei = ((size_t)b * 512 + u) * 1024 + t;
            g_et_hi[ei] = hh;
            g_et_lo[ei] = hl;
            __threadfence();
        }
        __syncthreads();

        // two-level monotonic barrier: 8 groups of 16 -> root
        if (tid == 0) {
            unsigned a = atomicAdd(&g_cnt[grp * 32], 1u);
            if (a == (unsigned)((t + 1) * 16 - 1)) atomicAdd(&g_root, 1u);
            while (*(volatile unsigned*)&g_root < 8u * (unsigned)(t + 1)) { }
        }
        __syncthreads();
    }
}

// ---------------- LSTM-2: 4 independent warps (one per batch) ----------------
__global__ __launch_bounds__(128)
void k_lstm2(const float* __restrict__ Wp_hh,
             const float* __restrict__ Wmu, const float* __restrict__ bmu,
             const float* __restrict__ Wsig, const float* __restrict__ bsig,
             const int* __restrict__ pad)
{
    __shared__ float wp[1600];
    __shared__ float wmu_s[60];
    __shared__ float wsig_s[20];
    __shared__ float bconst[4];
    __shared__ float hp[4][20];
    __shared__ float gp[4][80];
    __shared__ float tmp[4][4];
    const int tid = threadIdx.x;
    const int b = tid >> 5, lane = tid & 31;

    for (int i = tid; i < 1600; i += 128) wp[i] = Wp_hh[i];
    for (int i = tid; i < 60; i += 128) wmu_s[i] = Wmu[i];
    if (tid < 20) wsig_s[tid] = Wsig[tid];
    if (tid < 3) bconst[tid] = bmu[tid];
    if (tid == 3) bconst[3] = bsig[0];
    if (tid < 80) hp[tid / 20][tid % 20] = 0.f;
    __syncthreads();

    const float invL = 1.f / (float)pad[b];
    float cc = 0.f;
    float mu_prev = 0.f;
    const int r0 = lane, r1 = lane + 32, r2 = lane + 64;
    const int r2c = (r2 < 80) ? r2 : 79;

    float px0 = g_pxw[(size_t)(b * T_) * 128 + r0];
    float px1 = g_pxw[(size_t)(b * T_) * 128 + r1];
    float px2 = (r2 < 80) ? g_pxw[(size_t)(b * T_) * 128 + r2] : 0.f;

    for (int t = 0; t < T_; ++t) {
        float s0 = px0, s1 = px1, s2 = px2;
#pragma unroll
        for (int k = 0; k < 20; ++k) {
            float h = hp[b][k];
            s0 = fmaf(wp[r0 * 20 + k], h, s0);
            s1 = fmaf(wp[r1 * 20 + k], h, s1);
            s2 = fmaf(wp[r2c * 20 + k], h, s2);
        }
        gp[b][r0] = s0;
        gp[b][r1] = s1;
        if (r2 < 80) gp[b][r2] = s2;
        if (t + 1 < T_) {
            size_t base = (size_t)(b * T_ + t + 1) * 128;
            px0 = g_pxw[base + r0];
            px1 = g_pxw[base + r1];
            if (r2 < 80) px2 = g_pxw[base + r2];
        }
        __syncwarp();
        if (lane < 20) {
            float gi = gp[b][lane], gf = gp[b][20 + lane];
            float gg = gp[b][40 + lane], go = gp[b][60 + lane];
            cc = sigf(gf) * cc + sigf(gi) * tfast(gg);
            hp[b][lane] = sigf(go) * tfast(cc);
        }
        __syncwarp();
        if (lane >= 20 && lane < 24) {
            int s = lane - 20;
            const float* wv = (s < 3) ? &wmu_s[s * 20] : wsig_s;
            float acc = bconst[s];
#pragma unroll
            for (int k = 0; k < 20; ++k) acc = fmaf(wv[k], hp[b][k], acc);
            tmp[b][s] = acc;
        }
        __syncwarp();
        if (lane == 0) {
            float m0 = fmaxf(tmp[b][0], 0.f);
            float m1 = fmaxf(tmp[b][1], 0.f);
            float m2 = fmaxf(tmp[b][2], 0.f);
            float sg = sigf(tmp[b][3]);
            float mu = fmaf(m0, mu_prev, (m1 + m2 * (float)(t + 1)) * invL);
            mu_prev = mu;
            g_mu[b * T_ + t]  = mu;
            g_sig[b * T_ + t] = sg;
        }
    }
}

// ---------------- attention weights: compute, normalize, split to bf16 ------------
__global__ __launch_bounds__(256)
void k_wnorm()
{
    __shared__ float wsm[1024];
    __shared__ float red[8];
    const int tid = threadIdx.x, lane = tid & 31, warp = tid >> 5;
    const int bj = blockIdx.x;
    const int b = bj >> 10, j = bj & 1023;
    const float mu = g_mu[bj];
    const float sg = g_sig[bj];
    const float invd  = 1.f / (2.f * sg * sg + 0.001f);
    const float invj1 = 1.f / (float)(j + 1);

    float lsum = 0.f;
#pragma unroll
    for (int i = 0; i < 4; ++i) {
        int t = tid + i * 256;
        float w = 0.f;
        if (t <= j) {
            float r = (float)t * invj1 - mu;
            w = __expf(-r * r * invd);
        }
        wsm[t] = w;
        lsum += w;
    }
    lsum += __shfl_xor_sync(0xffffffffu, lsum, 16);
    lsum += __shfl_xor_sync(0xffffffffu, lsum, 8);
    lsum += __shfl_xor_sync(0xffffffffu, lsum, 4);
    lsum += __shfl_xor_sync(0xffffffffu, lsum, 2);
    lsum += __shfl_xor_sync(0xffffffffu, lsum, 1);
    if (lane == 0) red[warp] = lsum;
    __syncthreads();
    float tot = red[0] + red[1] + red[2] + red[3] + red[4] + red[5] + red[6] + red[7];
    const float scale = 1.f / fmaxf(tot, 1e-12f);

    size_t base = ((size_t)b << 20) + ((size_t)j << 10);
#pragma unroll
    for (int i = 0; i < 4; ++i) {
        int t = tid + i * 256;
        float v = wsm[t] * scale;
        bf16 h = __float2bfloat16(v);
        g_w_hi[base + t] = h;
        g_w_lo[base + t] = __float2bfloat16(v - __bfloat162float(h));
    }
}

// ---------------- launch ----------------
extern "C" void kernel_launch(void* const* d_in, const int* in_sizes, int n_in,
                              void* d_out, int out_size)
{
    const int*   ids      = (const int*)d_in[0];
    const int*   pad      = (const int*)d_in[1];
    const float* emb      = (const float*)d_in[2];
    const float* dec_bias = (const float*)d_in[3];
    const float* Wih      = (const float*)d_in[4];
    const float* Whh      = (const float*)d_in[5];
    const float* bih      = (const float*)d_in[6];
    const float* bhh      = (const float*)d_in[7];
    const float* Wp_ih    = (const float*)d_in[8];
    const float* Wp_hh    = (const float*)d_in[9];
    const float* bp_ih    = (const float*)d_in[10];
    const float* bp_hh    = (const float*)d_in[11];
    const float* Wmu      = (const float*)d_in[12];
    const float* bmu      = (const float*)d_in[13];
    const float* Wsig     = (const float*)d_in[14];
    const float* bsig     = (const float*)d_in[15];
    const float* Wc       = (const float*)d_in[16];
    const float* bc       = (const float*)d_in[17];
    float* out = (float*)d_out;

    float *p_xw, *p_pxw, *p_bp;
    bf16 *p_ehi, *p_elo, *p_whi, *p_wlo, *p_xhi, *p_xlo;
    bf16 *p_nhi, *p_nlo, *p_ethi, *p_etlo, *p_awhi, *p_awlo;
    bf16 *p_cxhi, *p_cxlo, *p_cbhi, *p_cblo, *p_wchi, *p_wclo, *p_wphi, *p_wplo;
    cudaGetSymbolAddress((void**)&p_xw,    g_xw);
    cudaGetSymbolAddress((void**)&p_pxw,   g_pxw);
    cudaGetSymbolAddress((void**)&p_bp,    g_bp);
    cudaGetSymbolAddress((void**)&p_ehi,   g_emb_hi);
    cudaGetSymbolAddress((void**)&p_elo,   g_emb_lo);
    cudaGetSymbolAddress((void**)&p_whi,   g_wih_hi);
    cudaGetSymbolAddress((void**)&p_wlo,   g_wih_lo);
    cudaGetSymbolAddress((void**)&p_xhi,   g_x_hi);
    cudaGetSymbolAddress((void**)&p_xlo,   g_x_lo);
    cudaGetSymbolAddress((void**)&p_nhi,   g_enc_hi);
    cudaGetSymbolAddress((void**)&p_nlo,   g_enc_lo);
    cudaGetSymbolAddress((void**)&p_ethi,  g_et_hi);
    cudaGetSymbolAddress((void**)&p_etlo,  g_et_lo);
    cudaGetSymbolAddress((void**)&p_awhi,  g_w_hi);
    cudaGetSymbolAddress((void**)&p_awlo,  g_w_lo);
    cudaGetSymbolAddress((void**)&p_cxhi,  g_ctx_hi);
    cudaGetSymbolAddress((void**)&p_cxlo,  g_ctx_lo);
    cudaGetSymbolAddress((void**)&p_cbhi,  g_comb_hi);
    cudaGetSymbolAddress((void**)&p_cblo,  g_comb_lo);
    cudaGetSymbolAddress((void**)&p_wchi,  g_wc_hi);
    cudaGetSymbolAddress((void**)&p_wclo,  g_wc_lo);
    cudaGetSymbolAddress((void**)&p_wphi,  g_wp_hi);
    cudaGetSymbolAddress((void**)&p_wplo,  g_wp_lo);

    cudaFuncSetAttribute(k_mma, cudaFuncAttributeMaxDynamicSharedMemorySize, MMA_SMEM);

    const int NOB = 1 << 28;  // "no batching"

    // weight / input splits
    k_split<<<(V_ * H_ + 255) / 256, 256>>>(emb, p_ehi, p_elo, V_ * H_);
    k_split<<<(4 * H_ * H_ + 255) / 256, 256>>>(Wih, p_whi, p_wlo, 4 * H_ * H_);
    k_split<<<(H_ * 2 * H_ + 255) / 256, 256>>>(Wc, p_wchi, p_wclo, H_ * 2 * H_);
    k_split<<<(80 * H_ + 255) / 256, 256>>>(Wp_ih, p_wphi, p_wplo, 80 * H_);
    k_padbias<<<1, 128>>>(bp_ih, bp_hh);
    k_embed_bf<<<(BT * H_ + 255) / 256, 256>>>(ids);

    // K1: xw = x @ Wih^T + bih + bhh -> fp32 [4096, 2048]
    k_mma<<<dim3(16, 32), 256, MMA_SMEM>>>(
        p_xhi, p_xlo, 512, nullptr, nullptr, 0, 8, 8, NOB, 0,
        p_whi, p_wlo, 512, 0, 2048, bih, bhh, p_xw, nullptr, nullptr, 0);

    // K2: LSTM-1 recurrence -> enc (fp32 + bf16 hi/lo row & transposed)
    k_lstm1<<<NB1, 256>>>(Whh);

    // K3: pxw = enc @ Wp_ih^T + biases -> fp32 [4096, 128pad]
    k_mma<<<dim3(1, 32), 256, MMA_SMEM>>>(
        p_nhi, p_nlo, 512, nullptr, nullptr, 0, 8, 8, NOB, 0,
        p_wphi, p_wplo, 512, 0, 128, p_bp, nullptr, p_pxw, nullptr, nullptr, 0);

    // K4: LSTM-2 + mu/sigma scan
    k_lstm2<<<1, 128>>>(Wp_hh, Wmu, bmu, Wsig, bsig, pad);

    // K5a: attention weights (normalized, bf16 hi/lo)
    k_wnorm<<<BT, 256>>>();

    // K5b: ctx = w @ enc (batched) -> bf16 hi/lo [4096, 512]
    k_mma<<<dim3(4, 32), 256, MMA_SMEM>>>(
        p_awhi, p_awlo, 1024, nullptr, nullptr, 0, 16, 16, 8, (size_t)T_ * T_,
        p_ethi, p_etlo, 1024, (size_t)H_ * T_, 512,
        nullptr, nullptr, nullptr, p_cxhi, p_cxlo, 0);

    // K6: combined = tanh([ctx, enc] @ Wc^T + bc) -> bf16 hi/lo [4096, 512]
    k_mma<<<dim3(4, 32), 256, MMA_SMEM>>>(
        p_cxhi, p_cxlo, 512, p_nhi, p_nlo, 512, 8, 16, NOB, 0,
        p_wchi, p_wclo, 1024, 0, 512, bc, nullptr, nullptr, p_cbhi, p_cblo, 1);

    // K7: logits = combined @ emb^T + dec_bias -> fp32 [4096, 32000]
    k_mma<<<dim3(250, 32), 256, MMA_SMEM>>>(
        p_cbhi, p_cblo, 512, nullptr, nullptr, 0, 8, 8, NOB, 0,
        p_ehi, p_elo, 512, 0, V_, dec_bias, nullptr, out, nullptr, nullptr, 0);
}